// round 14
// baseline (speedup 1.0000x reference)
#include <cuda_runtime.h>
#include <cuda_fp16.h>
#include <mma.h>

using namespace nvcuda;

#define BATCH 8
#define HEADS 16
#define SEQ 1024
#define HD 64
#define QTILE 32
#define CH 128
#define NCH (SEQ / CH) /* 8 */
#define NTHREADS 512

#define SLD 1040 /* score ldm (half) */
#define KLD 72   /* q/k/v ldm (half) */
#define OLD 72   /* out staging ldm (float) */

#define INV_T 0.125f
#define INV1023 (1.0f / 1023.0f)

/* smem layout (bytes) — 106 KB/CTA -> 2 CTAs/SM (two independent barrier domains) */
#define OFF_S 0
#define SZ_S (QTILE * SLD * 2) /* 66560 */
#define OFF_K (OFF_S + SZ_S)
#define SZ_K (2 * CH * KLD * 2) /* 36864 */
#define OFF_Q (OFF_K + SZ_K)
#define SZ_Q (QTILE * KLD * 2) /* 4608 */
#define OFF_R (OFF_Q + SZ_Q)
#define SZ_R (QTILE * 4) /* 128 */
#define OFF_C (OFF_R + SZ_R)
#define SZ_C (HD * 4)
#define SMEM_TOTAL (OFF_C + SZ_C) /* 108416 */

struct ChunkRegs { float4 v[4]; };

/* 512 threads: thread = (r0 = tid>>4 in 0..31, cq = tid&15); rows r0+32*ro */
__device__ __forceinline__ void chunk_ld(const float* __restrict__ src, int tid, ChunkRegs& r) {
    int cq = tid & 15;
    int r0 = tid >> 4;
#pragma unroll
    for (int ro = 0; ro < 4; ro++)
        r.v[ro] = *(const float4*)(src + (r0 + 32 * ro) * HD + cq * 4);
}

__device__ __forceinline__ void chunk_st(half* __restrict__ dst, int tid, const ChunkRegs& r) {
    int cq = tid & 15;
    int r0 = tid >> 4;
#pragma unroll
    for (int ro = 0; ro < 4; ro++) {
        float4 f = r.v[ro];
        half* p = dst + (r0 + 32 * ro) * KLD + cq * 4;
        *(__half2*)p = __floats2half2_rn(f.x, f.y);
        *(__half2*)(p + 2) = __floats2half2_rn(f.z, f.w);
    }
}

__device__ __forceinline__ void chunk_st_cs(half* __restrict__ dst, int tid, const ChunkRegs& r,
                                            float4& cs) {
    int cq = tid & 15;
    int r0 = tid >> 4;
#pragma unroll
    for (int ro = 0; ro < 4; ro++) {
        float4 f = r.v[ro];
        cs.x += f.x; cs.y += f.y; cs.z += f.z; cs.w += f.w;
        half* p = dst + (r0 + 32 * ro) * KLD + cq * 4;
        *(__half2*)p = __floats2half2_rn(f.x, f.y);
        *(__half2*)(p + 2) = __floats2half2_rn(f.z, f.w);
    }
}

/* attn = (1 - e*rinv)/1023 for chunk j. Warp w owns rows 2w, 2w+1.
   Per row: 32 lanes cover the 128 cols (lane*4) -> coalesced float4 streaming
   stores. No P is materialized: PV is computed as diag(rinv) * (E V). */
__device__ __forceinline__ void attn_write(const half* __restrict__ sS,
                                           float* __restrict__ attn_g, int j, int w, int lane,
                                           const float* rinv2) {
#pragma unroll
    for (int r2 = 0; r2 < 2; r2++) {
        int row = w * 2 + r2;
        const __half2* sp = (const __half2*)(sS + row * SLD + j * CH) + lane * 2;
        float rinv = rinv2[r2];
        float2 f0 = __half22float2(sp[0]);
        float2 f1 = __half22float2(sp[1]);
        float4 av;
        av.x = (1.0f - f0.x * rinv) * INV1023;
        av.y = (1.0f - f0.y * rinv) * INV1023;
        av.z = (1.0f - f1.x * rinv) * INV1023;
        av.w = (1.0f - f1.y * rinv) * INV1023;
        __stcs((float4*)(attn_g + (size_t)row * SEQ + j * CH + lane * 4), av);
    }
}

__global__ void __launch_bounds__(NTHREADS, 2)
rca_attn_kernel(const float* __restrict__ q, const float* __restrict__ k,
                const float* __restrict__ v, float* __restrict__ out) {
    extern __shared__ char smem[];
    half* sS = (half*)(smem + OFF_S);          /* [QTILE][SLD] scores -> exp(s) */
    half* sK = (half*)(smem + OFF_K);          /* [2][CH][KLD]  (k then v chunks) */
    half* sQ = (half*)(smem + OFF_Q);          /* [QTILE][KLD] */
    float* sRinv = (float*)(smem + OFF_R);     /* [QTILE] */
    float* sCol = (float*)(smem + OFF_C);      /* [HD] colsum of v */
    float* sOutF = (float*)(smem + OFF_S);     /* alias: [2][QTILE][OLD] EV staging */

    int tid = threadIdx.x;
    int w = tid >> 5;
    int lane = tid & 31;

    int bx = blockIdx.x;
    int bh = bx >> 5;          /* 32 q-tiles per head now */
    int qt = bx & 31;
    size_t bhBase = (size_t)bh * (SEQ * HD);
    const float* qg = q + bhBase + (size_t)qt * QTILE * HD;
    const float* kg = k + bhBase;
    const float* vg = v + bhBase;
    float* outO = out + bhBase + (size_t)qt * QTILE * HD;
    float* attnO = out + (size_t)BATCH * HEADS * SEQ * HD
                       + (size_t)bh * SEQ * SEQ + (size_t)qt * QTILE * SEQ;

    if (tid < HD) sCol[tid] = 0.0f;

    /* ---- load Q (scaled by 1/T): one float4 per thread ---- */
    {
        int row = tid >> 4;
        int qi = tid & 15;
        float4 f = *(const float4*)(qg + row * HD + qi * 4);
        half* p = sQ + row * KLD + qi * 4;
        *(__half2*)p = __floats2half2_rn(f.x * INV_T, f.y * INV_T);
        *(__half2*)(p + 2) = __floats2half2_rn(f.z * INV_T, f.w * INV_T);
    }

    /* ---- pass 1: scores = Q K^T into sS (fp16), prefetch-double-buffered.
       16 warps, one 16x16 tile per warp per chunk: rb = w>>3 (0..1), cb = w&7. */
    ChunkRegs cr;
    chunk_ld(kg, tid, cr);
    chunk_st(sK, tid, cr);
    __syncthreads();

    int rb = w >> 3;
    int cb = w & 7;

    wmma::fragment<wmma::matrix_a, 16, 16, 16, half, wmma::row_major> aq[4];
#pragma unroll
    for (int ks = 0; ks < 4; ks++)
        wmma::load_matrix_sync(aq[ks], sQ + (rb * 16) * KLD + ks * 16, KLD);

    for (int j = 0; j < NCH; j++) {
        if (j + 1 < NCH) chunk_ld(kg + (size_t)(j + 1) * CH * HD, tid, cr);
        const half* kb = sK + (j & 1) * CH * KLD;
        wmma::fragment<wmma::accumulator, 16, 16, 16, half> acc;
        wmma::fill_fragment(acc, __float2half(0.0f));
#pragma unroll
        for (int ks = 0; ks < 4; ks++) {
            wmma::fragment<wmma::matrix_b, 16, 16, 16, half, wmma::col_major> b;
            wmma::load_matrix_sync(b, kb + (cb * 16) * KLD + ks * 16, KLD);
            wmma::mma_sync(acc, aq[ks], b, acc);
        }
        wmma::store_matrix_sync(sS + (rb * 16) * SLD + j * CH + cb * 16,
                                acc, SLD, wmma::mem_row_major);
        if (j + 1 < NCH) chunk_st(sK + ((j + 1) & 1) * CH * KLD, tid, cr);
        __syncthreads();
    }

    /* ---- per-row sum of exp(s) (max-free: softmax shift-invariant, |s| <~ 6).
       Warp w owns rows 2w, 2w+1; exp written back in place. ---- */
    float rinv2[2];
#pragma unroll
    for (int r2 = 0; r2 < 2; r2++) {
        int row = w * 2 + r2;
        __half2* hp = (__half2*)(sS + row * SLD);
        float sum = 0.0f;
#pragma unroll
        for (int i = 0; i < 16; i++) {
            __half2 h = hp[lane + i * 32];
            float2 f = __half22float2(h);
            float e0 = __expf(f.x);
            float e1 = __expf(f.y);
            sum += e0 + e1;
            hp[lane + i * 32] = __floats2half2_rn(e0, e1);
        }
#pragma unroll
        for (int off = 16; off >= 1; off >>= 1)
            sum += __shfl_xor_sync(0xffffffffu, sum, off);
        rinv2[r2] = 1.0f / sum;
    }
    if (lane < 2) sRinv[2 * w + lane] = rinv2[lane];

    /* ---- pass 2: attn writes + EV = E V (E read straight from sS).
       8 output tiles (2x4), K-split across warp pairs:
       t = w>>1 (0..7), kh = w&1; rb2 = t>>2, cb2 = t&3. ---- */
    int t = w >> 1;
    int kh = w & 1;
    int rb2 = t >> 2;
    int cb2 = t & 3;

    wmma::fragment<wmma::accumulator, 16, 16, 16, float> accO;
    wmma::fill_fragment(accO, 0.0f);

    float4 cs = make_float4(0.f, 0.f, 0.f, 0.f);
    chunk_ld(vg, tid, cr);
    attn_write(sS, attnO, 0, w, lane, rinv2);
    chunk_st_cs(sK, tid, cr, cs);
    __syncthreads(); /* also orders all exp writes before cross-warp E reads */

    for (int j = 0; j < NCH; j++) {
        if (j + 1 < NCH) chunk_ld(vg + (size_t)(j + 1) * CH * HD, tid, cr);
        const half* vb = sK + (j & 1) * CH * KLD;
#pragma unroll
        for (int ks2 = 0; ks2 < 4; ks2++) {
            int ks = kh * 4 + ks2;
            wmma::fragment<wmma::matrix_a, 16, 16, 16, half, wmma::row_major> a;
            wmma::load_matrix_sync(a, sS + (rb2 * 16) * SLD + j * CH + ks * 16, SLD);
            wmma::fragment<wmma::matrix_b, 16, 16, 16, half, wmma::row_major> b;
            wmma::load_matrix_sync(b, vb + (ks * 16) * KLD + cb2 * 16, KLD);
            wmma::mma_sync(accO, a, b, accO);
        }
        if (j + 1 < NCH) {
            attn_write(sS, attnO, j + 1, w, lane, rinv2);
            chunk_st_cs(sK + ((j + 1) & 1) * CH * KLD, tid, cr, cs);
        }
        __syncthreads();
    }

    /* ---- colsum reduce + stage EV halves (alias sS; safe after final barrier),
       then out[r,d] = (colsum[d] - rinv[r]*(EV0+EV1)[r,d]) / 1023 ---- */
    {
        int cq = tid & 15;
        atomicAdd(&sCol[cq * 4 + 0], cs.x);
        atomicAdd(&sCol[cq * 4 + 1], cs.y);
        atomicAdd(&sCol[cq * 4 + 2], cs.z);
        atomicAdd(&sCol[cq * 4 + 3], cs.w);
    }
    wmma::store_matrix_sync(sOutF + kh * (QTILE * OLD) + (rb2 * 16) * OLD + cb2 * 16,
                            accO, OLD, wmma::mem_row_major);
    __syncthreads();

    {
        int row = tid >> 4;
        int c = (tid & 15) * 4;
        float rinv = sRinv[row];
        const float* s0 = sOutF + row * OLD;
        const float* s1 = sOutF + QTILE * OLD + row * OLD;
        float4 o;
        o.x = (sCol[c + 0] - (s0[c + 0] + s1[c + 0]) * rinv) * INV1023;
        o.y = (sCol[c + 1] - (s0[c + 1] + s1[c + 1]) * rinv) * INV1023;
        o.z = (sCol[c + 2] - (s0[c + 2] + s1[c + 2]) * rinv) * INV1023;
        o.w = (sCol[c + 3] - (s0[c + 3] + s1[c + 3]) * rinv) * INV1023;
        *(float4*)(outO + row * HD + c) = o;
    }
}

extern "C" void kernel_launch(void* const* d_in, const int* in_sizes, int n_in,
                              void* d_out, int out_size) {
    const float* q = (const float*)d_in[0];
    const float* k = (const float*)d_in[1];
    const float* v = (const float*)d_in[2];
    float* out = (float*)d_out;

    cudaFuncSetAttribute(rca_attn_kernel, cudaFuncAttributeMaxDynamicSharedMemorySize,
                         SMEM_TOTAL);
    dim3 grid(BATCH * HEADS * (SEQ / QTILE)); /* 4096 */
    rca_attn_kernel<<<grid, NTHREADS, SMEM_TOTAL>>>(q, k, v, out);
}

// round 15
// speedup vs baseline: 1.2605x; 1.2605x over previous
#include <cuda_runtime.h>
#include <cuda_fp16.h>
#include <mma.h>

using namespace nvcuda;

#define BATCH 8
#define HEADS 16
#define SEQ 1024
#define HD 64
#define QTILE 64
#define CH 128
#define NCH (SEQ / CH) /* 8 */
#define NTHREADS 512

#define SLD 1032 /* score ldm (half); 2064B stride == 16 mod 128 -> conflict-free ldmatrix */
#define KLD 72   /* q/k/v ldm (half) */
#define OLD 72   /* out staging ldm (float) */

#define INV_T 0.125f
#define INV1023 (1.0f / 1023.0f)

/* smem layout (bytes) — ~178 KB/CTA, 1 CTA/SM */
#define OFF_S 0
#define SZ_S (QTILE * SLD * 2) /* 132096 */
#define OFF_K (OFF_S + SZ_S)
#define SZ_K (2 * CH * KLD * 2) /* 36864 */
#define OFF_Q (OFF_K + SZ_K)
#define SZ_Q (QTILE * KLD * 2) /* 9216 */
#define OFF_R (OFF_Q + SZ_Q)
#define SZ_R (QTILE * 4) /* 256 */
#define OFF_C (OFF_R + SZ_R)
#define SZ_C (HD * 4)
#define SMEM_TOTAL (OFF_C + SZ_C) /* 178688 */

struct ChunkRegs { float4 v[4]; };

/* 512 threads: thread = (r0 = tid>>4 in 0..31, cq = tid&15); rows r0+32*ro */
__device__ __forceinline__ void chunk_ld(const float* __restrict__ src, int tid, ChunkRegs& r) {
    int cq = tid & 15;
    int r0 = tid >> 4;
#pragma unroll
    for (int ro = 0; ro < 4; ro++)
        r.v[ro] = *(const float4*)(src + (r0 + 32 * ro) * HD + cq * 4);
}

__device__ __forceinline__ void chunk_st(half* __restrict__ dst, int tid, const ChunkRegs& r) {
    int cq = tid & 15;
    int r0 = tid >> 4;
#pragma unroll
    for (int ro = 0; ro < 4; ro++) {
        float4 f = r.v[ro];
        half* p = dst + (r0 + 32 * ro) * KLD + cq * 4;
        *(__half2*)p = __floats2half2_rn(f.x, f.y);
        *(__half2*)(p + 2) = __floats2half2_rn(f.z, f.w);
    }
}

__device__ __forceinline__ void chunk_st_cs(half* __restrict__ dst, int tid, const ChunkRegs& r,
                                            float4& cs) {
    int cq = tid & 15;
    int r0 = tid >> 4;
#pragma unroll
    for (int ro = 0; ro < 4; ro++) {
        float4 f = r.v[ro];
        cs.x += f.x; cs.y += f.y; cs.z += f.z; cs.w += f.w;
        half* p = dst + (r0 + 32 * ro) * KLD + cq * 4;
        *(__half2*)p = __floats2half2_rn(f.x, f.y);
        *(__half2*)(p + 2) = __floats2half2_rn(f.z, f.w);
    }
}

/* attn = (1 - e*rinv)/1023 for chunk j. Warp w owns rows 4w..4w+3.
   Per row: 32 lanes cover 128 cols (lane*4) -> coalesced float4 streaming stores.
   P never materialized: out uses diag(rinv) * (E V) in the epilogue. */
__device__ __forceinline__ void attn_write(const half* __restrict__ sS,
                                           float* __restrict__ attn_g, int j, int w, int lane,
                                           const float* rinv4) {
#pragma unroll
    for (int r4 = 0; r4 < 4; r4++) {
        int row = w * 4 + r4;
        const __half2* sp = (const __half2*)(sS + row * SLD + j * CH) + lane * 2;
        float rinv = rinv4[r4];
        float2 f0 = __half22float2(sp[0]);
        float2 f1 = __half22float2(sp[1]);
        float4 av;
        av.x = (1.0f - f0.x * rinv) * INV1023;
        av.y = (1.0f - f0.y * rinv) * INV1023;
        av.z = (1.0f - f1.x * rinv) * INV1023;
        av.w = (1.0f - f1.y * rinv) * INV1023;
        __stcs((float4*)(attn_g + (size_t)row * SEQ + j * CH + lane * 4), av);
    }
}

__global__ void __launch_bounds__(NTHREADS, 1)
rca_attn_kernel(const float* __restrict__ q, const float* __restrict__ k,
                const float* __restrict__ v, float* __restrict__ out) {
    extern __shared__ char smem[];
    half* sS = (half*)(smem + OFF_S);          /* [QTILE][SLD] exp(scores) */
    half* sK = (half*)(smem + OFF_K);          /* [2][CH][KLD]  (k then v chunks) */
    half* sQ = (half*)(smem + OFF_Q);          /* [QTILE][KLD] */
    float* sRinv = (float*)(smem + OFF_R);     /* [QTILE] */
    float* sCol = (float*)(smem + OFF_C);      /* [HD] colsum of v */
    float* sOutF = (float*)(smem + OFF_S);     /* alias: [QTILE][OLD] EV staging */

    int tid = threadIdx.x;
    int w = tid >> 5;
    int lane = tid & 31;
    int rb = w >> 2;       /* warp row-block 0..3 */
    int cp = w & 3;        /* warp column quarter 0..3 */

    int bx = blockIdx.x;
    int bh = bx >> 4;
    int qt = bx & 15;
    size_t bhBase = (size_t)bh * (SEQ * HD);
    const float* qg = q + bhBase + (size_t)qt * QTILE * HD;
    const float* kg = k + bhBase;
    const float* vg = v + bhBase;
    float* outO = out + bhBase + (size_t)qt * QTILE * HD;
    float* attnO = out + (size_t)BATCH * HEADS * SEQ * HD
                       + (size_t)bh * SEQ * SEQ + (size_t)qt * QTILE * SEQ;

    if (tid < HD) sCol[tid] = 0.0f;

    /* ---- load Q (scaled by 1/T) ---- */
    {
        int row = tid >> 3;
#pragma unroll
        for (int i = 0; i < 2; i++) {
            int qi = (tid & 7) + 8 * i;
            float4 f = *(const float4*)(qg + row * HD + qi * 4);
            half* p = sQ + row * KLD + qi * 4;
            *(__half2*)p = __floats2half2_rn(f.x * INV_T, f.y * INV_T);
            *(__half2*)(p + 2) = __floats2half2_rn(f.z * INV_T, f.w * INV_T);
        }
    }

    /* ---- pass 1: sS = exp(Q K^T), exp fused on accumulator fragments.
       16 warps, 2 tiles/warp/chunk: rows rb*16, cols (cp*2+t)*16. ---- */
    ChunkRegs cr;
    chunk_ld(kg, tid, cr);
    chunk_st(sK, tid, cr);
    __syncthreads();

    wmma::fragment<wmma::matrix_a, 16, 16, 16, half, wmma::row_major> aq[4];
#pragma unroll
    for (int ks = 0; ks < 4; ks++)
        wmma::load_matrix_sync(aq[ks], sQ + (rb * 16) * KLD + ks * 16, KLD);

    for (int j = 0; j < NCH; j++) {
        if (j + 1 < NCH) chunk_ld(kg + (size_t)(j + 1) * CH * HD, tid, cr);
        const half* kb = sK + (j & 1) * CH * KLD;
#pragma unroll
        for (int t = 0; t < 2; t++) {
            int cb = cp * 2 + t;
            wmma::fragment<wmma::accumulator, 16, 16, 16, half> acc;
            wmma::fill_fragment(acc, __float2half(0.0f));
#pragma unroll
            for (int ks = 0; ks < 4; ks++) {
                wmma::fragment<wmma::matrix_b, 16, 16, 16, half, wmma::col_major> b;
                wmma::load_matrix_sync(b, kb + (cb * 16) * KLD + ks * 16, KLD);
                wmma::mma_sync(acc, aq[ks], b, acc);
            }
            /* exp in registers (layout-agnostic elementwise) -> sS holds E */
#pragma unroll
            for (int e = 0; e < acc.num_elements; e++)
                acc.x[e] = __float2half(__expf(__half2float(acc.x[e])));
            wmma::store_matrix_sync(sS + (rb * 16) * SLD + j * CH + cb * 16,
                                    acc, SLD, wmma::mem_row_major);
        }
        if (j + 1 < NCH) chunk_st(sK + ((j + 1) & 1) * CH * KLD, tid, cr);
        __syncthreads();
    }

    /* ---- read-only row-sum sweep (exp already applied in pass 1).
       Warp w owns rows 4w..4w+3; max-free softmax (shift-invariant, |s| <~ 6). */
    float rinv4[4];
#pragma unroll
    for (int r4 = 0; r4 < 4; r4++) {
        int row = w * 4 + r4;
        const __half2* hp = (const __half2*)(sS + row * SLD);
        float sum = 0.0f;
#pragma unroll
        for (int i = 0; i < 16; i++) {
            float2 f = __half22float2(hp[lane + i * 32]);
            sum += f.x + f.y;
        }
#pragma unroll
        for (int off = 16; off >= 1; off >>= 1)
            sum += __shfl_xor_sync(0xffffffffu, sum, off);
        rinv4[r4] = 1.0f / sum;
    }
    if (lane < 4) sRinv[w * 4 + lane] = rinv4[lane];

    /* ---- pass 2: attn writes + EV = E V (A read straight from sS).
       16 tiles (4x4), one per warp: rows rb*16, cols cp*16. ---- */
    wmma::fragment<wmma::accumulator, 16, 16, 16, float> accO;
    wmma::fill_fragment(accO, 0.0f);

    float4 cs = make_float4(0.f, 0.f, 0.f, 0.f);
    chunk_ld(vg, tid, cr);
    attn_write(sS, attnO, 0, w, lane, rinv4);
    chunk_st_cs(sK, tid, cr, cs);
    __syncthreads();

    for (int j = 0; j < NCH; j++) {
        if (j + 1 < NCH) chunk_ld(vg + (size_t)(j + 1) * CH * HD, tid, cr);
        const half* vb = sK + (j & 1) * CH * KLD;
#pragma unroll
        for (int ks = 0; ks < 8; ks++) {
            wmma::fragment<wmma::matrix_a, 16, 16, 16, half, wmma::row_major> a;
            wmma::load_matrix_sync(a, sS + (rb * 16) * SLD + j * CH + ks * 16, SLD);
            wmma::fragment<wmma::matrix_b, 16, 16, 16, half, wmma::row_major> b;
            wmma::load_matrix_sync(b, vb + (ks * 16) * KLD + cp * 16, KLD);
            wmma::mma_sync(accO, a, b, accO);
        }
        if (j + 1 < NCH) {
            attn_write(sS, attnO, j + 1, w, lane, rinv4);
            chunk_st_cs(sK + ((j + 1) & 1) * CH * KLD, tid, cr, cs);
        }
        __syncthreads();
    }

    /* ---- colsum reduce + stage EV (alias sS; safe after final barrier),
       then out[r,d] = (colsum[d] - rinv[r]*EV[r,d]) / 1023 ---- */
    {
        int cq = tid & 15;
        atomicAdd(&sCol[cq * 4 + 0], cs.x);
        atomicAdd(&sCol[cq * 4 + 1], cs.y);
        atomicAdd(&sCol[cq * 4 + 2], cs.z);
        atomicAdd(&sCol[cq * 4 + 3], cs.w);
    }
    wmma::store_matrix_sync(sOutF + (rb * 16) * OLD + cp * 16, accO, OLD, wmma::mem_row_major);
    __syncthreads();

    {
        int row = tid >> 3;
        int c0 = (tid & 7) * 8;
        float rinv = sRinv[row];
#pragma unroll
        for (int i = 0; i < 2; i++) {
            int c = c0 + 4 * i;
            const float* s0 = sOutF + row * OLD;
            float4 o;
            o.x = (sCol[c + 0] - s0[c + 0] * rinv) * INV1023;
            o.y = (sCol[c + 1] - s0[c + 1] * rinv) * INV1023;
            o.z = (sCol[c + 2] - s0[c + 2] * rinv) * INV1023;
            o.w = (sCol[c + 3] - s0[c + 3] * rinv) * INV1023;
            *(float4*)(outO + row * HD + c) = o;
        }
    }
}

extern "C" void kernel_launch(void* const* d_in, const int* in_sizes, int n_in,
                              void* d_out, int out_size) {
    const float* q = (const float*)d_in[0];
    const float* k = (const float*)d_in[1];
    const float* v = (const float*)d_in[2];
    float* out = (float*)d_out;

    cudaFuncSetAttribute(rca_attn_kernel, cudaFuncAttributeMaxDynamicSharedMemorySize,
                         SMEM_TOTAL);
    dim3 grid(BATCH * HEADS * (SEQ / QTILE)); /* 2048 */
    rca_attn_kernel<<<grid, NTHREADS, SMEM_TOTAL>>>(q, k, v, out);
}

// round 17
// speedup vs baseline: 1.3365x; 1.0603x over previous
#include <cuda_runtime.h>
#include <cuda_fp16.h>
#include <cstdint>
#include <mma.h>

using namespace nvcuda;

#define BATCH 8
#define HEADS 16
#define SEQ 1024
#define HD 64
#define QTILE 64
#define CH 128
#define NCH (SEQ / CH) /* 8 */
#define NTHREADS 512

#define SLD 1032 /* score ldm (half); stride == 16B mod 128 -> 2-way max on ldmatrix */
#define KLD 72   /* k/v ldm (half) */
#define OLD 72   /* out staging ldm (float) */

#define INV_T 0.125f
#define INV1023 (1.0f / 1023.0f)

/* smem layout (bytes) — ~178 KB/CTA, 1 CTA/SM */
#define OFF_S 0
#define SZ_S (QTILE * SLD * 2) /* 132096 */
#define OFF_K (OFF_S + SZ_S)
#define SZ_K (2 * CH * KLD * 2) /* 36864 */
#define OFF_Q (OFF_K + SZ_K)
#define SZ_Q (QTILE * KLD * 2) /* 9216 */
#define OFF_R (OFF_Q + SZ_Q)
#define SZ_R (QTILE * 4) /* 256 */
#define OFF_C (OFF_R + SZ_R)
#define SZ_C (HD * 4)
#define SMEM_TOTAL (OFF_C + SZ_C) /* 178688 */

#define CHBUF (CH * KLD * 2) /* 18432 bytes per chunk buffer */

/* fp16 K/V scratch + fp32 V-colsum partials (prep kernel -> main kernel) */
__device__ __half d_kh[(size_t)BATCH * HEADS * SEQ * HD];
__device__ __half d_vh[(size_t)BATCH * HEADS * SEQ * HD];
__device__ float d_csum[BATCH * HEADS * 8 * HD];

/* ---- prep: fp32 -> fp16 K/V scratch + exact fp32 V colsums ---- */
__global__ void __launch_bounds__(256) prep_kernel(const float* __restrict__ k,
                                                   const float* __restrict__ v) {
    int bh = blockIdx.x >> 3;
    int rc = blockIdx.x & 7;
    size_t base = (size_t)bh * SEQ * HD + (size_t)rc * 128 * HD;
    const float* kg = k + base;
    const float* vg = v + base;
    __half* khp = d_kh + base;
    __half* vhp = d_vh + base;
    __shared__ float scol[HD];
    int tid = threadIdx.x;
    if (tid < HD) scol[tid] = 0.0f;
    __syncthreads();
    int cq = tid & 15, r0 = tid >> 4;
    float4 cs = make_float4(0.f, 0.f, 0.f, 0.f);
#pragma unroll
    for (int ro = 0; ro < 8; ro++) {
        int row = r0 + 16 * ro;
        float4 f = *(const float4*)(kg + row * HD + cq * 4);
        __half2* kp = (__half2*)(khp + row * HD + cq * 4);
        kp[0] = __floats2half2_rn(f.x, f.y);
        kp[1] = __floats2half2_rn(f.z, f.w);
        float4 g = *(const float4*)(vg + row * HD + cq * 4);
        cs.x += g.x; cs.y += g.y; cs.z += g.z; cs.w += g.w;
        __half2* vp = (__half2*)(vhp + row * HD + cq * 4);
        vp[0] = __floats2half2_rn(g.x, g.y);
        vp[1] = __floats2half2_rn(g.z, g.w);
    }
    atomicAdd(&scol[cq * 4 + 0], cs.x);
    atomicAdd(&scol[cq * 4 + 1], cs.y);
    atomicAdd(&scol[cq * 4 + 2], cs.z);
    atomicAdd(&scol[cq * 4 + 3], cs.w);
    __syncthreads();
    if (tid < HD) d_csum[blockIdx.x * HD + tid] = scol[tid];
}

/* ---- cp.async helpers ---- */
__device__ __forceinline__ void cp16(uint32_t s, const void* g) {
    asm volatile("cp.async.cg.shared.global [%0], [%1], 16;" :: "r"(s), "l"(g) : "memory");
}
__device__ __forceinline__ void cp_commit() { asm volatile("cp.async.commit_group;" ::: "memory"); }
__device__ __forceinline__ void cp_wait1() { asm volatile("cp.async.wait_group 1;" ::: "memory"); }
__device__ __forceinline__ void cp_wait0() { asm volatile("cp.async.wait_group 0;" ::: "memory"); }

/* stage one 128x64 fp16 chunk: 1024 16B-transfers, 2 per thread */
__device__ __forceinline__ void stage_chunk(uint32_t sbase, const __half* __restrict__ g,
                                            int tid) {
    int i0 = tid;
    cp16(sbase + (i0 >> 3) * (KLD * 2) + (i0 & 7) * 16, g + (i0 >> 3) * HD + (i0 & 7) * 8);
    int i1 = tid + 512;
    cp16(sbase + (i1 >> 3) * (KLD * 2) + (i1 & 7) * 16, g + (i1 >> 3) * HD + (i1 & 7) * 8);
}

/* attn = (1 - e*rinv)/1023 for chunk j. Warp w owns rows 4w..4w+3. */
__device__ __forceinline__ void attn_write(const half* __restrict__ sS,
                                           float* __restrict__ attn_g, int j, int w, int lane,
                                           const float* rinv4) {
#pragma unroll
    for (int r4 = 0; r4 < 4; r4++) {
        int row = w * 4 + r4;
        const __half2* sp = (const __half2*)(sS + row * SLD + j * CH) + lane * 2;
        float rinv = rinv4[r4];
        float2 f0 = __half22float2(sp[0]);
        float2 f1 = __half22float2(sp[1]);
        float4 av;
        av.x = (1.0f - f0.x * rinv) * INV1023;
        av.y = (1.0f - f0.y * rinv) * INV1023;
        av.z = (1.0f - f1.x * rinv) * INV1023;
        av.w = (1.0f - f1.y * rinv) * INV1023;
        __stcs((float4*)(attn_g + (size_t)row * SEQ + j * CH + lane * 4), av);
    }
}

__global__ void __launch_bounds__(NTHREADS, 1)
rca_attn_kernel(const float* __restrict__ q, float* __restrict__ out) {
    extern __shared__ char smem[];
    half* sS = (half*)(smem + OFF_S);          /* [QTILE][SLD] exp(scores) */
    half* sK = (half*)(smem + OFF_K);          /* [2][CH][KLD] (k then v chunks) */
    half* sQ = (half*)(smem + OFF_Q);          /* [QTILE][KLD] */
    float* sRinv = (float*)(smem + OFF_R);     /* [QTILE] */
    float* sCol = (float*)(smem + OFF_C);      /* [HD] colsum of v */
    float* sOutF = (float*)(smem + OFF_S);     /* alias: [QTILE][OLD] EV staging */

    int tid = threadIdx.x;
    int w = tid >> 5;
    int lane = tid & 31;
    int rb = w >> 2;
    int cp = w & 3;

    int bx = blockIdx.x;
    int bh = bx >> 4;
    int qt = bx & 15;
    size_t bhBase = (size_t)bh * (SEQ * HD);
    const float* qg = q + bhBase + (size_t)qt * QTILE * HD;
    const __half* kh = d_kh + bhBase;
    const __half* vh = d_vh + bhBase;
    float* outO = out + bhBase + (size_t)qt * QTILE * HD;
    float* attnO = out + (size_t)BATCH * HEADS * SEQ * HD
                       + (size_t)bh * SEQ * SEQ + (size_t)qt * QTILE * SEQ;

    uint32_t skAddr = (uint32_t)__cvta_generic_to_shared(sK);

    /* kick off chunk 0 of K immediately */
    stage_chunk(skAddr, kh, tid);
    cp_commit();

    /* colsum: sum 8 prep partials (fp32-exact) */
    if (tid < HD) {
        float s = 0.0f;
#pragma unroll
        for (int c = 0; c < 8; c++) s += d_csum[(bh * 8 + c) * HD + tid];
        sCol[tid] = s;
    }

    /* load Q (scaled by 1/T) */
    {
        int row = tid >> 3;
#pragma unroll
        for (int i = 0; i < 2; i++) {
            int qi = (tid & 7) + 8 * i;
            float4 f = *(const float4*)(qg + row * HD + qi * 4);
            half* p = sQ + row * KLD + qi * 4;
            *(__half2*)p = __floats2half2_rn(f.x * INV_T, f.y * INV_T);
            *(__half2*)(p + 2) = __floats2half2_rn(f.z * INV_T, f.w * INV_T);
        }
    }

    /* ---- pass 1: sS = exp(Q K^T), exp fused on accumulator fragments ---- */
    cp_wait0();
    __syncthreads();

    wmma::fragment<wmma::matrix_a, 16, 16, 16, half, wmma::row_major> aq[4];
#pragma unroll
    for (int ks = 0; ks < 4; ks++)
        wmma::load_matrix_sync(aq[ks], sQ + (rb * 16) * KLD + ks * 16, KLD);

    for (int j = 0; j < NCH; j++) {
        if (j + 1 < NCH) {
            stage_chunk(skAddr + ((j + 1) & 1) * CHBUF, kh + (size_t)(j + 1) * CH * HD, tid);
            cp_commit();
            cp_wait1();
        } else {
            cp_wait0();
        }
        __syncthreads(); /* chunk j visible to all */
        const half* kb = sK + (j & 1) * CH * KLD;
#pragma unroll
        for (int t = 0; t < 2; t++) {
            int cb = cp * 2 + t;
            wmma::fragment<wmma::accumulator, 16, 16, 16, half> acc;
            wmma::fill_fragment(acc, __float2half(0.0f));
#pragma unroll
            for (int ks = 0; ks < 4; ks++) {
                wmma::fragment<wmma::matrix_b, 16, 16, 16, half, wmma::col_major> b;
                wmma::load_matrix_sync(b, kb + (cb * 16) * KLD + ks * 16, KLD);
                wmma::mma_sync(acc, aq[ks], b, acc);
            }
#pragma unroll
            for (int e = 0; e < acc.num_elements; e++)
                acc.x[e] = __float2half(__expf(__half2float(acc.x[e])));
            wmma::store_matrix_sync(sS + (rb * 16) * SLD + j * CH + cb * 16,
                                    acc, SLD, wmma::mem_row_major);
        }
        __syncthreads(); /* buffer j&1 free for reuse at next issue */
    }

    /* overlap V chunk 0 staging with the row-sum sweep */
    stage_chunk(skAddr, vh, tid);
    cp_commit();

    /* read-only row-sum sweep (exp already applied). Warp w owns rows 4w..4w+3. */
    float rinv4[4];
#pragma unroll
    for (int r4 = 0; r4 < 4; r4++) {
        int row = w * 4 + r4;
        const __half2* hp = (const __half2*)(sS + row * SLD);
        float sum = 0.0f;
#pragma unroll
        for (int i = 0; i < 16; i++) {
            float2 f = __half22float2(hp[lane + i * 32]);
            sum += f.x + f.y;
        }
#pragma unroll
        for (int off = 16; off >= 1; off >>= 1)
            sum += __shfl_xor_sync(0xffffffffu, sum, off);
        rinv4[r4] = 1.0f / sum;
    }
    if (lane < 4) sRinv[w * 4 + lane] = rinv4[lane];

    attn_write(sS, attnO, 0, w, lane, rinv4);

    /* ---- pass 2: attn writes + EV = E V, dual accumulators ---- */
    wmma::fragment<wmma::accumulator, 16, 16, 16, float> accO, accO2;
    wmma::fill_fragment(accO, 0.0f);
    wmma::fill_fragment(accO2, 0.0f);

    for (int j = 0; j < NCH; j++) {
        if (j + 1 < NCH) {
            stage_chunk(skAddr + ((j + 1) & 1) * CHBUF, vh + (size_t)(j + 1) * CH * HD, tid);
            cp_commit();
            cp_wait1();
        } else {
            cp_wait0();
        }
        __syncthreads();
        const half* vb = sK + (j & 1) * CH * KLD;
#pragma unroll
        for (int ks = 0; ks < 8; ks++) {
            wmma::fragment<wmma::matrix_a, 16, 16, 16, half, wmma::row_major> a;
            wmma::load_matrix_sync(a, sS + (rb * 16) * SLD + j * CH + ks * 16, SLD);
            wmma::fragment<wmma::matrix_b, 16, 16, 16, half, wmma::row_major> b;
            wmma::load_matrix_sync(b, vb + (ks * 16) * KLD + cp * 16, KLD);
            if (ks & 1) wmma::mma_sync(accO2, a, b, accO2);
            else        wmma::mma_sync(accO, a, b, accO);
        }
        if (j + 1 < NCH) attn_write(sS, attnO, j + 1, w, lane, rinv4);
        __syncthreads();
    }

    /* ---- stage EV (alias sS; safe after final barrier), then
       out[r,d] = (colsum[d] - rinv[r]*EV[r,d]) / 1023 ---- */
#pragma unroll
    for (int e = 0; e < accO.num_elements; e++) accO.x[e] += accO2.x[e];
    wmma::store_matrix_sync(sOutF + (rb * 16) * OLD + cp * 16, accO, OLD, wmma::mem_row_major);
    __syncthreads();

    {
        int row = tid >> 3;
        int c0 = (tid & 7) * 8;
        float rinv = sRinv[row];
#pragma unroll
        for (int i = 0; i < 2; i++) {
            int c = c0 + 4 * i;
            const float* s0 = sOutF + row * OLD;
            float4 o;
            o.x = (sCol[c + 0] - s0[c + 0] * rinv) * INV1023;
            o.y = (sCol[c + 1] - s0[c + 1] * rinv) * INV1023;
            o.z = (sCol[c + 2] - s0[c + 2] * rinv) * INV1023;
            o.w = (sCol[c + 3] - s0[c + 3] * rinv) * INV1023;
            *(float4*)(outO + row * HD + c) = o;
        }
    }
}

extern "C" void kernel_launch(void* const* d_in, const int* in_sizes, int n_in,
                              void* d_out, int out_size) {
    const float* q = (const float*)d_in[0];
    const float* k = (const float*)d_in[1];
    const float* v = (const float*)d_in[2];
    float* out = (float*)d_out;

    prep_kernel<<<BATCH * HEADS * 8, 256>>>(k, v);

    cudaFuncSetAttribute(rca_attn_kernel, cudaFuncAttributeMaxDynamicSharedMemorySize,
                         SMEM_TOTAL);
    dim3 grid(BATCH * HEADS * (SEQ / QTILE)); /* 2048 */
    rca_attn_kernel<<<grid, NTHREADS, SMEM_TOTAL>>>(q, out);
}